// round 14
// baseline (speedup 1.0000x reference)
#include <cuda_runtime.h>
#include <cuda_bf16.h>
#include <cstdint>
#include <math.h>

// Problem constants
#define B_     4096
#define D_     784
#define HALF_  392
#define HID_   512
#define CONDN_ 10
#define NBLK_  20

#define K1PAD  416          // 392 padded to 13*32
#define K2PAD  512
#define N2PAD  832          // 416 (s,t)-pairs * 2

// GEMM tiling: CTA 128(M) x 64(N) x 32(K-stage), 8 warps of 32x32, 3-stage pipeline
#define TILE_M 128
#define TILE_N 64
#define TILE_K 32
#define STAGES 3

// smem stage layout (bytes): rows padded 64B->80B for conflict-free ldmatrix
#define SA_ROW   80
#define ST_AHI   0
#define ST_ALO   10240
#define ST_BHI   20480
#define ST_BLO   25600
#define ST_SIZE  30720
#define SM_TOTAL (STAGES * ST_SIZE)

// ---------------- PTX helpers ----------------
__device__ __forceinline__ uint32_t smem_u32(const void* p) {
    uint32_t a;
    asm("{ .reg .u64 t; cvta.to.shared.u64 t, %1; cvt.u32.u64 %0, t; }" : "=r"(a) : "l"(p));
    return a;
}
#define CP_ASYNC16(dst, src) \
    asm volatile("cp.async.cg.shared.global [%0], [%1], 16;" :: "r"(dst), "l"(src))
#define CP_COMMIT() asm volatile("cp.async.commit_group;" ::: "memory")
#define CP_WAIT1()  asm volatile("cp.async.wait_group 1;" ::: "memory")

__device__ __forceinline__ void ldm4(uint32_t& r0, uint32_t& r1, uint32_t& r2, uint32_t& r3,
                                     uint32_t a) {
    asm volatile("ldmatrix.sync.aligned.m8n8.x4.shared.b16 {%0,%1,%2,%3}, [%4];"
                 : "=r"(r0), "=r"(r1), "=r"(r2), "=r"(r3) : "r"(a));
}
__device__ __forceinline__ void mma_bf16(float& c0, float& c1, float& c2, float& c3,
                                         uint32_t a0, uint32_t a1, uint32_t a2, uint32_t a3,
                                         uint32_t b0, uint32_t b1) {
    asm volatile(
        "mma.sync.aligned.m16n8k16.row.col.f32.bf16.bf16.f32 "
        "{%0,%1,%2,%3}, {%4,%5,%6,%7}, {%8,%9}, {%0,%1,%2,%3};"
        : "+f"(c0), "+f"(c1), "+f"(c2), "+f"(c3)
        : "r"(a0), "r"(a1), "r"(a2), "r"(a3), "r"(b0), "r"(b1));
}

// ---------------- device scratch ----------------
__device__ float g_v [B_ * D_];
__device__ float g_xa[B_ * HALF_];
__device__ float g_xb[B_ * HALF_];

__device__ __nv_bfloat16 g_xbh[B_ * K1PAD];
__device__ __nv_bfloat16 g_xbl[B_ * K1PAD];
__device__ __nv_bfloat16 g_ysh[B_ * K1PAD];
__device__ __nv_bfloat16 g_ysl[B_ * K1PAD];
__device__ __nv_bfloat16 g_hh [B_ * K2PAD];
__device__ __nv_bfloat16 g_hl [B_ * K2PAD];

// transposed + split weights: W1t [blk][512][416], W2t interleaved [blk][832][512]
__device__ __nv_bfloat16 g_s1w1_hi[NBLK_ * HID_ * K1PAD];
__device__ __nv_bfloat16 g_s1w1_lo[NBLK_ * HID_ * K1PAD];
__device__ __nv_bfloat16 g_s2w1_hi[NBLK_ * HID_ * K1PAD];
__device__ __nv_bfloat16 g_s2w1_lo[NBLK_ * HID_ * K1PAD];
__device__ __nv_bfloat16 g_s1w2_hi[NBLK_ * N2PAD * K2PAD];
__device__ __nv_bfloat16 g_s1w2_lo[NBLK_ * N2PAD * K2PAD];
__device__ __nv_bfloat16 g_s2w2_hi[NBLK_ * N2PAD * K2PAD];
__device__ __nv_bfloat16 g_s2w2_lo[NBLK_ * N2PAD * K2PAD];

__device__ __forceinline__ void split1(float v, __nv_bfloat16& h, __nv_bfloat16& l) {
    h = __float2bfloat16_rn(v);
    l = __float2bfloat16_rn(v - __bfloat162float(h));
}

// ---------------- small kernels ----------------
// zero jac + zero K-pad columns of split activation buffers
__global__ void init_kernel(float* __restrict__ jac,
                            __nv_bfloat16* __restrict__ xbh, __nv_bfloat16* __restrict__ xbl,
                            __nv_bfloat16* __restrict__ ysh, __nv_bfloat16* __restrict__ ysl) {
    int idx = blockIdx.x * blockDim.x + threadIdx.x;
    if (idx < B_) jac[idx] = 0.f;
    if (idx < B_ * (K1PAD - HALF_)) {
        int i = idx / (K1PAD - HALF_);
        int jj = HALF_ + idx % (K1PAD - HALF_);
        __nv_bfloat16 zz = __float2bfloat16_rn(0.f);
        size_t o = (size_t)i * K1PAD + jj;
        xbh[o] = zz; xbl[o] = zz; ysh[o] = zz; ysl[o] = zz;
    }
}

// permute + split second half (operates on nrows rows; pointers pre-offset)
__global__ void permute_kernel(const float* __restrict__ v,
                               const int* __restrict__ perm,
                               float* __restrict__ xa,
                               float* __restrict__ xb,
                               __nv_bfloat16* __restrict__ xbh,
                               __nv_bfloat16* __restrict__ xbl,
                               int nrows) {
    int idx = blockIdx.x * blockDim.x + threadIdx.x;
    if (idx >= nrows * D_) return;
    int i = idx / D_;
    int j = idx - i * D_;
    float val = v[(size_t)i * D_ + perm[j]];
    if (j < HALF_) {
        xa[(size_t)i * HALF_ + j] = val;
    } else {
        int jj = j - HALF_;
        xb[(size_t)i * HALF_ + jj] = val;
        __nv_bfloat16 h, l;
        split1(val, h, l);
        xbh[(size_t)i * K1PAD + jj] = h;
        xbl[(size_t)i * K1PAD + jj] = l;
    }
}

// transpose + split W1 (both subnets via grid.z): [blk][402][512] -> [blk][512][416]
__global__ void convert_w1_kernel(const float* __restrict__ Ws1, const float* __restrict__ Ws2,
                                  __nv_bfloat16* __restrict__ hi1, __nv_bfloat16* __restrict__ lo1,
                                  __nv_bfloat16* __restrict__ hi2, __nv_bfloat16* __restrict__ lo2) {
    __shared__ float t[16][17];
    int zz = blockIdx.z;
    int sel = zz >= NBLK_;
    int blk = sel ? zz - NBLK_ : zz;
    const float* W = sel ? Ws2 : Ws1;
    __nv_bfloat16* hi = sel ? hi2 : hi1;
    __nv_bfloat16* lo = sel ? lo2 : lo1;
    int bk = blockIdx.x;
    int bn = blockIdx.y;
    int tx = threadIdx.x & 15, ty = threadIdx.x >> 4;
    int k = bk * 16 + ty, n = bn * 16 + tx;
    float v = (k < HALF_) ? W[((size_t)blk * (HALF_ + CONDN_) + k) * HID_ + n] : 0.f;
    t[ty][tx] = v;
    __syncthreads();
    float o = t[tx][ty];
    __nv_bfloat16 h, l;
    split1(o, h, l);
    size_t oidx = ((size_t)blk * HID_ + bn * 16 + ty) * K1PAD + bk * 16 + tx;
    hi[oidx] = h;
    lo[oidx] = l;
}

// transpose + split + (s,t)-interleave W2: [blk][512][784] -> [blk][832][512]
__global__ void convert_w2_kernel(const float* __restrict__ Ws1, const float* __restrict__ Ws2,
                                  __nv_bfloat16* __restrict__ hi1, __nv_bfloat16* __restrict__ lo1,
                                  __nv_bfloat16* __restrict__ hi2, __nv_bfloat16* __restrict__ lo2) {
    __shared__ float t[16][17];
    int zz = blockIdx.z;
    int sel = zz >= NBLK_;
    int blk = sel ? zz - NBLK_ : zz;
    const float* W = sel ? Ws2 : Ws1;
    __nv_bfloat16* hi = sel ? hi2 : hi1;
    __nv_bfloat16* lo = sel ? lo2 : lo1;
    int bk = blockIdx.x;
    int bn = blockIdx.y;
    int tx = threadIdx.x & 15, ty = threadIdx.x >> 4;
    int k = bk * 16 + ty;
    int nOut = bn * 16 + tx;
    int p = nOut >> 1;
    int orig = (nOut & 1) ? (HALF_ + p) : p;
    float v = (p < HALF_) ? W[((size_t)blk * HID_ + k) * D_ + orig] : 0.f;
    t[ty][tx] = v;
    __syncthreads();
    float o = t[tx][ty];
    __nv_bfloat16 h, l;
    split1(o, h, l);
    size_t oidx = ((size_t)blk * N2PAD + bn * 16 + ty) * K2PAD + bk * 16 + tx;
    hi[oidx] = h;
    lo[oidx] = l;
}

// ---------------- fused HMMA GEMM (3-stage pipeline, 1 sync/chunk, 2 CTAs/SM) ----------------
// MODE 0: hidden layer. C = relu(A@Bt^T + bias + Wcond[392+lab[m]]), write split bf16.
// MODE 1/2: output layer, interleaved (s,t) columns, fused coupling:
//   p = n/2; s = acc(n)+bias[p]; t = acc(n+1)+bias[392+p];
//   ls = 0.636*atan(s); y = exp(ls)*xo[m][p] + t; Yf[m*D_+p] = y; jac[m] += ls;
//   MODE 1 additionally writes split bf16 y (Chi/Clo stride K1PAD).
template<int MODE>
__global__ __launch_bounds__(256, 2)
void gemm_mma(const __nv_bfloat16* __restrict__ Ahi, const __nv_bfloat16* __restrict__ Alo,
              const __nv_bfloat16* __restrict__ Bhi, const __nv_bfloat16* __restrict__ Blo,
              int Ka, int nch,
              const float* __restrict__ bias,
              const float* __restrict__ Wcond, const int* __restrict__ lab,
              const float* __restrict__ xo,
              float* __restrict__ Yf, float* __restrict__ jac,
              __nv_bfloat16* __restrict__ Chi, __nv_bfloat16* __restrict__ Clo) {
    extern __shared__ __align__(128) char sm[];
    const int tid = threadIdx.x;
    const int lane = tid & 31, wid = tid >> 5;
    const int wm = wid & 3, wn = wid >> 2;           // 4x2 warp grid, 32x32 warp tiles
    const int m0 = blockIdx.y * TILE_M, n0 = blockIdx.x * TILE_N;
    const uint32_t sb = smem_u32(sm);

    const int a_row = tid >> 2, a_seg = tid & 3;
    const int b_row = tid >> 2, b_seg = tid & 3;

    float acc[2][4][4];
#pragma unroll
    for (int i = 0; i < 2; i++)
#pragma unroll
        for (int j = 0; j < 4; j++)
#pragma unroll
            for (int q = 0; q < 4; q++) acc[i][j][q] = 0.f;

#define LOAD_STAGE(c, s)                                                                  \
    do {                                                                                  \
        uint32_t st = sb + (s) * ST_SIZE;                                                 \
        const __nv_bfloat16* a0s = Ahi + (size_t)(m0 + a_row) * Ka + (c) * 32 + a_seg * 8;\
        const __nv_bfloat16* a1s = a0s + (size_t)64 * Ka;                                 \
        const __nv_bfloat16* a2s = Alo + (size_t)(m0 + a_row) * Ka + (c) * 32 + a_seg * 8;\
        const __nv_bfloat16* a3s = a2s + (size_t)64 * Ka;                                 \
        CP_ASYNC16(st + ST_AHI + a_row * SA_ROW + a_seg * 16, a0s);                       \
        CP_ASYNC16(st + ST_AHI + (a_row + 64) * SA_ROW + a_seg * 16, a1s);                \
        CP_ASYNC16(st + ST_ALO + a_row * SA_ROW + a_seg * 16, a2s);                       \
        CP_ASYNC16(st + ST_ALO + (a_row + 64) * SA_ROW + a_seg * 16, a3s);                \
        CP_ASYNC16(st + ST_BHI + b_row * SA_ROW + b_seg * 16,                             \
                   Bhi + (size_t)(n0 + b_row) * Ka + (c) * 32 + b_seg * 8);               \
        CP_ASYNC16(st + ST_BLO + b_row * SA_ROW + b_seg * 16,                             \
                   Blo + (size_t)(n0 + b_row) * Ka + (c) * 32 + b_seg * 8);               \
    } while (0)

    LOAD_STAGE(0, 0);
    CP_COMMIT();
    LOAD_STAGE(1, 1);
    CP_COMMIT();

    const uint32_t a_lrow = (lane & 15);
    const uint32_t a_lcol = (lane >> 4) << 4;
    const uint32_t b_lrow = (lane & 7) + ((lane & 16) >> 1);
    const uint32_t b_lcol = (lane & 8) << 1;

    int cs = 0, ls2 = 2;
    for (int c = 0; c < nch; c++) {
        CP_WAIT1();            // in-order retirement: stage c resident
        __syncthreads();       // all warps done with stage (c-1)%3; safe to overwrite
        if (c + 2 < nch) LOAD_STAGE(c + 2, ls2);
        CP_COMMIT();           // commit (possibly empty) keeps group count in sync

        uint32_t st = sb + cs * ST_SIZE;
#pragma unroll
        for (int s = 0; s < 2; s++) {
            uint32_t a[2][2][4];
            uint32_t b[2][4][2];
#pragma unroll
            for (int hl = 0; hl < 2; hl++) {
#pragma unroll
                for (int mm = 0; mm < 2; mm++) {
                    uint32_t ad = st + (hl ? ST_ALO : ST_AHI)
                                + (wm * 32 + mm * 16 + a_lrow) * SA_ROW + a_lcol + s * 32;
                    ldm4(a[hl][mm][0], a[hl][mm][1], a[hl][mm][2], a[hl][mm][3], ad);
                }
#pragma unroll
                for (int nt = 0; nt < 2; nt++) {
                    uint32_t bd = st + (hl ? ST_BLO : ST_BHI)
                                + (wn * 32 + nt * 16 + b_lrow) * SA_ROW + b_lcol + s * 32;
                    ldm4(b[hl][2 * nt][0], b[hl][2 * nt][1],
                         b[hl][2 * nt + 1][0], b[hl][2 * nt + 1][1], bd);
                }
            }
#pragma unroll
            for (int mm = 0; mm < 2; mm++) {
#pragma unroll
                for (int nn = 0; nn < 4; nn++) {
                    float* cc = acc[mm][nn];
                    mma_bf16(cc[0], cc[1], cc[2], cc[3],
                             a[0][mm][0], a[0][mm][1], a[0][mm][2], a[0][mm][3],
                             b[0][nn][0], b[0][nn][1]);
                    mma_bf16(cc[0], cc[1], cc[2], cc[3],
                             a[0][mm][0], a[0][mm][1], a[0][mm][2], a[0][mm][3],
                             b[1][nn][0], b[1][nn][1]);
                    mma_bf16(cc[0], cc[1], cc[2], cc[3],
                             a[1][mm][0], a[1][mm][1], a[1][mm][2], a[1][mm][3],
                             b[0][nn][0], b[0][nn][1]);
                }
            }
        }
        cs = (cs == STAGES - 1) ? 0 : cs + 1;
        ls2 = (ls2 == STAGES - 1) ? 0 : ls2 + 1;
    }
#undef LOAD_STAGE

    // ---- epilogue ----
    const int rbase = lane >> 2;
    const int cbase = (lane & 3) * 2;

    if (MODE == 0) {
#pragma unroll
        for (int mm = 0; mm < 2; mm++) {
#pragma unroll
            for (int h = 0; h < 2; h++) {
                int m = m0 + wm * 32 + mm * 16 + rbase + h * 8;
                const float* wc = Wcond + (size_t)(HALF_ + lab[m]) * HID_;
#pragma unroll
                for (int nn = 0; nn < 4; nn++) {
                    int n = n0 + wn * 32 + nn * 8 + cbase;
                    float v0 = acc[mm][nn][h * 2 + 0] + bias[n] + wc[n];
                    float v1 = acc[mm][nn][h * 2 + 1] + bias[n + 1] + wc[n + 1];
                    v0 = fmaxf(v0, 0.f);
                    v1 = fmaxf(v1, 0.f);
                    __nv_bfloat16 h0, l0, h1, l1;
                    split1(v0, h0, l0);
                    split1(v1, h1, l1);
                    __nv_bfloat162 hp; hp.x = h0; hp.y = h1;
                    __nv_bfloat162 lp; lp.x = l0; lp.y = l1;
                    *reinterpret_cast<__nv_bfloat162*>(Chi + (size_t)m * HID_ + n) = hp;
                    *reinterpret_cast<__nv_bfloat162*>(Clo + (size_t)m * HID_ + n) = lp;
                }
            }
        }
    } else {
#pragma unroll
        for (int mm = 0; mm < 2; mm++) {
#pragma unroll
            for (int h = 0; h < 2; h++) {
                int m = m0 + wm * 32 + mm * 16 + rbase + h * 8;
                float jl = 0.f;
#pragma unroll
                for (int nn = 0; nn < 4; nn++) {
                    int n = n0 + wn * 32 + nn * 8 + cbase;   // always even
                    int p = n >> 1;
                    if (p < HALF_) {
                        float s = acc[mm][nn][h * 2 + 0] + bias[p];
                        float t = acc[mm][nn][h * 2 + 1] + bias[HALF_ + p];
                        float ls = 0.636f * atanf(s);
                        float y = expf(ls) * xo[(size_t)m * HALF_ + p] + t;
                        Yf[(size_t)m * D_ + p] = y;
                        if (MODE == 1) {
                            __nv_bfloat16 yhh, yll;
                            split1(y, yhh, yll);
                            Chi[(size_t)m * K1PAD + p] = yhh;
                            Clo[(size_t)m * K1PAD + p] = yll;
                        }
                        jl += ls;
                    }
                }
                jl += __shfl_xor_sync(0xffffffffu, jl, 1);
                jl += __shfl_xor_sync(0xffffffffu, jl, 2);
                if ((lane & 3) == 0) atomicAdd(&jac[m], jl);
            }
        }
    }
}

// ---------------- host launcher ----------------
extern "C" void kernel_launch(void* const* d_in, const int* in_sizes, int n_in,
                              void* d_out, int out_size) {
    const float* x     = (const float*)d_in[0];
    const int*   l     = (const int*)  d_in[1];
    const int*   perms = (const int*)  d_in[2];
    const float* s1_W1 = (const float*)d_in[3];
    const float* s1_b1 = (const float*)d_in[4];
    const float* s1_W2 = (const float*)d_in[5];
    const float* s1_b2 = (const float*)d_in[6];
    const float* s2_W1 = (const float*)d_in[7];
    const float* s2_b1 = (const float*)d_in[8];
    const float* s2_W2 = (const float*)d_in[9];
    const float* s2_b2 = (const float*)d_in[10];

    float* z   = (float*)d_out;
    float* jac = z + (size_t)B_ * D_;

    float *pv, *pxa, *pxb;
    cudaGetSymbolAddress((void**)&pv,  g_v);
    cudaGetSymbolAddress((void**)&pxa, g_xa);
    cudaGetSymbolAddress((void**)&pxb, g_xb);

    __nv_bfloat16 *xbh, *xbl, *ysh, *ysl, *hh, *hl;
    cudaGetSymbolAddress((void**)&xbh, g_xbh);
    cudaGetSymbolAddress((void**)&xbl, g_xbl);
    cudaGetSymbolAddress((void**)&ysh, g_ysh);
    cudaGetSymbolAddress((void**)&ysl, g_ysl);
    cudaGetSymbolAddress((void**)&hh,  g_hh);
    cudaGetSymbolAddress((void**)&hl,  g_hl);

    __nv_bfloat16 *w1h[2], *w1l[2], *w2h[2], *w2l[2];
    cudaGetSymbolAddress((void**)&w1h[0], g_s1w1_hi);
    cudaGetSymbolAddress((void**)&w1l[0], g_s1w1_lo);
    cudaGetSymbolAddress((void**)&w1h[1], g_s2w1_hi);
    cudaGetSymbolAddress((void**)&w1l[1], g_s2w1_lo);
    cudaGetSymbolAddress((void**)&w2h[0], g_s1w2_hi);
    cudaGetSymbolAddress((void**)&w2l[0], g_s1w2_lo);
    cudaGetSymbolAddress((void**)&w2h[1], g_s2w2_hi);
    cudaGetSymbolAddress((void**)&w2l[1], g_s2w2_lo);

    cudaFuncSetAttribute(gemm_mma<0>, cudaFuncAttributeMaxDynamicSharedMemorySize, SM_TOTAL);
    cudaFuncSetAttribute(gemm_mma<1>, cudaFuncAttributeMaxDynamicSharedMemorySize, SM_TOTAL);
    cudaFuncSetAttribute(gemm_mma<2>, cudaFuncAttributeMaxDynamicSharedMemorySize, SM_TOTAL);

    // persistent side streams/events (created once; deterministic work per call)
    static cudaStream_t st[2];
    static cudaEvent_t evFork, evJ[2];
    static bool inited = false;
    if (!inited) {
        for (int i = 0; i < 2; i++) {
            cudaStreamCreateWithFlags(&st[i], cudaStreamNonBlocking);
            cudaEventCreateWithFlags(&evJ[i], cudaEventDisableTiming);
        }
        cudaEventCreateWithFlags(&evFork, cudaEventDisableTiming);
        inited = true;
    }

    // ---- shared prologue on origin stream ----
    convert_w1_kernel<<<dim3(K1PAD / 16, HID_ / 16, 2 * NBLK_), 256>>>(
        s1_W1, s2_W1, w1h[0], w1l[0], w1h[1], w1l[1]);
    convert_w2_kernel<<<dim3(K2PAD / 16, N2PAD / 16, 2 * NBLK_), 256>>>(
        s1_W2, s2_W2, w2h[0], w2l[0], w2h[1], w2l[1]);
    init_kernel<<<(B_ * (K1PAD - HALF_) + 255) / 256, 256>>>(jac, xbh, xbl, ysh, ysl);

    // ---- fork: side streams wait on prologue; origin stream runs chain 0 ----
    cudaEventRecord(evFork, 0);
    cudaStreamWaitEvent(st[0], evFork, 0);
    cudaStreamWaitEvent(st[1], evFork, 0);

    // chain row split (multiples of TILE_M): 1408 / 1408 / 1280
    const int rowsArr[3] = {1408, 1408, 1280};
    const int offArr[3]  = {0, 1408, 2816};
    cudaStream_t strArr[3] = {(cudaStream_t)0, st[0], st[1]};

    const size_t W1sz  = (size_t)(HALF_ + CONDN_) * HID_;
    const size_t W1tsz = (size_t)HID_ * K1PAD;
    const size_t W2tsz = (size_t)N2PAD * K2PAD;

    for (int c = 0; c < 3; c++) {
        cudaStream_t s = strArr[c];
        const int rows = rowsArr[c];
        const size_t off = (size_t)offArr[c];

        const dim3 g1Grid(HID_ / TILE_N,  rows / TILE_M);
        const dim3 g2Grid(N2PAD / TILE_N, rows / TILE_M);
        const int permGrid = (rows * D_ + 255) / 256;

        const float* xH  = x   + off * D_;
        float* pvH       = pv  + off * D_;
        float* zH        = z   + off * D_;
        float* jacH      = jac + off;
        const int* lH    = l   + off;
        float* xaH = pxa + off * HALF_;
        float* xbH = pxb + off * HALF_;
        __nv_bfloat16* xbhH = xbh + off * K1PAD;
        __nv_bfloat16* xblH = xbl + off * K1PAD;
        __nv_bfloat16* yshH = ysh + off * K1PAD;
        __nv_bfloat16* yslH = ysl + off * K1PAD;
        __nv_bfloat16* hhH  = hh  + off * K2PAD;
        __nv_bfloat16* hlH  = hl  + off * K2PAD;

        for (int k = 0; k < NBLK_; k++) {
            const float* vsrc = (k == 0) ? xH : pvH;
            float* vdst = (k == NBLK_ - 1) ? zH : pvH;

            permute_kernel<<<permGrid, 256, 0, s>>>(
                vsrc, perms + (size_t)k * D_, xaH, xbH, xbhH, xblH, rows);

            // subnet s2: hidden, then output+coupling -> y1 (fp32 vdst + split)
            gemm_mma<0><<<g1Grid, 256, SM_TOTAL, s>>>(
                xbhH, xblH, w1h[1] + k * W1tsz, w1l[1] + k * W1tsz, K1PAD, K1PAD / TILE_K,
                s2_b1 + (size_t)k * HID_, s2_W1 + k * W1sz, lH,
                nullptr, nullptr, nullptr, hhH, hlH);
            gemm_mma<1><<<g2Grid, 256, SM_TOTAL, s>>>(
                hhH, hlH, w2h[1] + k * W2tsz, w2l[1] + k * W2tsz, K2PAD, K2PAD / TILE_K,
                s2_b2 + (size_t)k * D_, nullptr, nullptr,
                xaH, vdst, jacH, yshH, yslH);

            // subnet s1: hidden, then output+coupling -> y2 (fp32 vdst+HALF_)
            gemm_mma<0><<<g1Grid, 256, SM_TOTAL, s>>>(
                yshH, yslH, w1h[0] + k * W1tsz, w1l[0] + k * W1tsz, K1PAD, K1PAD / TILE_K,
                s1_b1 + (size_t)k * HID_, s1_W1 + k * W1sz, lH,
                nullptr, nullptr, nullptr, hhH, hlH);
            gemm_mma<2><<<g2Grid, 256, SM_TOTAL, s>>>(
                hhH, hlH, w2h[0] + k * W2tsz, w2l[0] + k * W2tsz, K2PAD, K2PAD / TILE_K,
                s1_b2 + (size_t)k * D_, nullptr, nullptr,
                xbH, vdst + HALF_, jacH, nullptr, nullptr);
        }
    }

    // ---- join side streams into origin ----
    cudaEventRecord(evJ[0], st[0]);
    cudaEventRecord(evJ[1], st[1]);
    cudaStreamWaitEvent(0, evJ[0], 0);
    cudaStreamWaitEvent(0, evJ[1], 0);
}

// round 15
// speedup vs baseline: 1.0157x; 1.0157x over previous
#include <cuda_runtime.h>
#include <cuda_bf16.h>
#include <cstdint>
#include <math.h>

// Problem constants
#define B_     4096
#define D_     784
#define HALF_  392
#define HID_   512
#define CONDN_ 10
#define NBLK_  20

#define K1PAD  416          // 392 padded to 13*32
#define K2PAD  512
#define N2PAD  832          // 416 (s,t)-pairs * 2

// GEMM tiling: CTA 128(M) x 64(N) x 32(K-stage), 8 warps of 32x32, 3-stage pipeline
#define TILE_M 128
#define TILE_N 64
#define TILE_K 32
#define STAGES 3

// smem stage layout (bytes): rows padded 64B->80B for conflict-free ldmatrix
#define SA_ROW   80
#define ST_AHI   0
#define ST_ALO   10240
#define ST_BHI   20480
#define ST_BLO   25600
#define ST_SIZE  30720
#define SM_TOTAL (STAGES * ST_SIZE)

// ---------------- PTX helpers ----------------
__device__ __forceinline__ uint32_t smem_u32(const void* p) {
    uint32_t a;
    asm("{ .reg .u64 t; cvta.to.shared.u64 t, %1; cvt.u32.u64 %0, t; }" : "=r"(a) : "l"(p));
    return a;
}
#define CP_ASYNC16(dst, src) \
    asm volatile("cp.async.cg.shared.global [%0], [%1], 16;" :: "r"(dst), "l"(src))
#define CP_COMMIT() asm volatile("cp.async.commit_group;" ::: "memory")
#define CP_WAIT1()  asm volatile("cp.async.wait_group 1;" ::: "memory")

__device__ __forceinline__ void ldm4(uint32_t& r0, uint32_t& r1, uint32_t& r2, uint32_t& r3,
                                     uint32_t a) {
    asm volatile("ldmatrix.sync.aligned.m8n8.x4.shared.b16 {%0,%1,%2,%3}, [%4];"
                 : "=r"(r0), "=r"(r1), "=r"(r2), "=r"(r3) : "r"(a));
}
__device__ __forceinline__ void mma_bf16(float& c0, float& c1, float& c2, float& c3,
                                         uint32_t a0, uint32_t a1, uint32_t a2, uint32_t a3,
                                         uint32_t b0, uint32_t b1) {
    asm volatile(
        "mma.sync.aligned.m16n8k16.row.col.f32.bf16.bf16.f32 "
        "{%0,%1,%2,%3}, {%4,%5,%6,%7}, {%8,%9}, {%0,%1,%2,%3};"
        : "+f"(c0), "+f"(c1), "+f"(c2), "+f"(c3)
        : "r"(a0), "r"(a1), "r"(a2), "r"(a3), "r"(b0), "r"(b1));
}

// ---------------- device scratch ----------------
__device__ float g_v [B_ * D_];
__device__ float g_xa[B_ * HALF_];
__device__ float g_xb[B_ * HALF_];

__device__ __nv_bfloat16 g_xbh[B_ * K1PAD];
__device__ __nv_bfloat16 g_xbl[B_ * K1PAD];
__device__ __nv_bfloat16 g_ysh[B_ * K1PAD];
__device__ __nv_bfloat16 g_ysl[B_ * K1PAD];
__device__ __nv_bfloat16 g_hh [B_ * K2PAD];
__device__ __nv_bfloat16 g_hl [B_ * K2PAD];

// transposed + split weights: W1t [blk][512][416], W2t interleaved [blk][832][512]
__device__ __nv_bfloat16 g_s1w1_hi[NBLK_ * HID_ * K1PAD];
__device__ __nv_bfloat16 g_s1w1_lo[NBLK_ * HID_ * K1PAD];
__device__ __nv_bfloat16 g_s2w1_hi[NBLK_ * HID_ * K1PAD];
__device__ __nv_bfloat16 g_s2w1_lo[NBLK_ * HID_ * K1PAD];
__device__ __nv_bfloat16 g_s1w2_hi[NBLK_ * N2PAD * K2PAD];
__device__ __nv_bfloat16 g_s1w2_lo[NBLK_ * N2PAD * K2PAD];
__device__ __nv_bfloat16 g_s2w2_hi[NBLK_ * N2PAD * K2PAD];
__device__ __nv_bfloat16 g_s2w2_lo[NBLK_ * N2PAD * K2PAD];

__device__ __forceinline__ void split1(float v, __nv_bfloat16& h, __nv_bfloat16& l) {
    h = __float2bfloat16_rn(v);
    l = __float2bfloat16_rn(v - __bfloat162float(h));
}

// ---------------- small kernels ----------------
// zero jac + zero K-pad columns of split activation buffers
__global__ void init_kernel(float* __restrict__ jac,
                            __nv_bfloat16* __restrict__ xbh, __nv_bfloat16* __restrict__ xbl,
                            __nv_bfloat16* __restrict__ ysh, __nv_bfloat16* __restrict__ ysl) {
    int idx = blockIdx.x * blockDim.x + threadIdx.x;
    if (idx < B_) jac[idx] = 0.f;
    if (idx < B_ * (K1PAD - HALF_)) {
        int i = idx / (K1PAD - HALF_);
        int jj = HALF_ + idx % (K1PAD - HALF_);
        __nv_bfloat16 zz = __float2bfloat16_rn(0.f);
        size_t o = (size_t)i * K1PAD + jj;
        xbh[o] = zz; xbl[o] = zz; ysh[o] = zz; ysl[o] = zz;
    }
}

// permute + split second half — 4 elements per thread (MLP=4 gather, vector stores).
// D=784=196*4, HALF=392 divisible by 4 -> each quad lies entirely in one half.
#define DQ_ 196
__global__ void permute_kernel(const float* __restrict__ v,
                               const int* __restrict__ perm,
                               float* __restrict__ xa,
                               float* __restrict__ xb,
                               __nv_bfloat16* __restrict__ xbh,
                               __nv_bfloat16* __restrict__ xbl,
                               int nrows) {
    int t = blockIdx.x * blockDim.x + threadIdx.x;
    if (t >= nrows * DQ_) return;
    int i = t / DQ_;
    int j = (t - i * DQ_) * 4;
    const float* vrow = v + (size_t)i * D_;
    int4 p4 = *reinterpret_cast<const int4*>(perm + j);
    float4 val;
    val.x = vrow[p4.x];
    val.y = vrow[p4.y];
    val.z = vrow[p4.z];
    val.w = vrow[p4.w];
    if (j < HALF_) {
        *reinterpret_cast<float4*>(xa + (size_t)i * HALF_ + j) = val;
    } else {
        int jj = j - HALF_;
        *reinterpret_cast<float4*>(xb + (size_t)i * HALF_ + jj) = val;
        __nv_bfloat16 h0, l0, h1, l1, h2, l2, h3, l3;
        split1(val.x, h0, l0);
        split1(val.y, h1, l1);
        split1(val.z, h2, l2);
        split1(val.w, h3, l3);
        __nv_bfloat162 hA; hA.x = h0; hA.y = h1;
        __nv_bfloat162 hB; hB.x = h2; hB.y = h3;
        __nv_bfloat162 lA; lA.x = l0; lA.y = l1;
        __nv_bfloat162 lB; lB.x = l2; lB.y = l3;
        __nv_bfloat162* ph = reinterpret_cast<__nv_bfloat162*>(xbh + (size_t)i * K1PAD + jj);
        __nv_bfloat162* pl = reinterpret_cast<__nv_bfloat162*>(xbl + (size_t)i * K1PAD + jj);
        ph[0] = hA; ph[1] = hB;
        pl[0] = lA; pl[1] = lB;
    }
}

// transpose + split W1 (both subnets via grid.z): [blk][402][512] -> [blk][512][416]
__global__ void convert_w1_kernel(const float* __restrict__ Ws1, const float* __restrict__ Ws2,
                                  __nv_bfloat16* __restrict__ hi1, __nv_bfloat16* __restrict__ lo1,
                                  __nv_bfloat16* __restrict__ hi2, __nv_bfloat16* __restrict__ lo2) {
    __shared__ float t[16][17];
    int zz = blockIdx.z;
    int sel = zz >= NBLK_;
    int blk = sel ? zz - NBLK_ : zz;
    const float* W = sel ? Ws2 : Ws1;
    __nv_bfloat16* hi = sel ? hi2 : hi1;
    __nv_bfloat16* lo = sel ? lo2 : lo1;
    int bk = blockIdx.x;
    int bn = blockIdx.y;
    int tx = threadIdx.x & 15, ty = threadIdx.x >> 4;
    int k = bk * 16 + ty, n = bn * 16 + tx;
    float v = (k < HALF_) ? W[((size_t)blk * (HALF_ + CONDN_) + k) * HID_ + n] : 0.f;
    t[ty][tx] = v;
    __syncthreads();
    float o = t[tx][ty];
    __nv_bfloat16 h, l;
    split1(o, h, l);
    size_t oidx = ((size_t)blk * HID_ + bn * 16 + ty) * K1PAD + bk * 16 + tx;
    hi[oidx] = h;
    lo[oidx] = l;
}

// transpose + split + (s,t)-interleave W2: [blk][512][784] -> [blk][832][512]
__global__ void convert_w2_kernel(const float* __restrict__ Ws1, const float* __restrict__ Ws2,
                                  __nv_bfloat16* __restrict__ hi1, __nv_bfloat16* __restrict__ lo1,
                                  __nv_bfloat16* __restrict__ hi2, __nv_bfloat16* __restrict__ lo2) {
    __shared__ float t[16][17];
    int zz = blockIdx.z;
    int sel = zz >= NBLK_;
    int blk = sel ? zz - NBLK_ : zz;
    const float* W = sel ? Ws2 : Ws1;
    __nv_bfloat16* hi = sel ? hi2 : hi1;
    __nv_bfloat16* lo = sel ? lo2 : lo1;
    int bk = blockIdx.x;
    int bn = blockIdx.y;
    int tx = threadIdx.x & 15, ty = threadIdx.x >> 4;
    int k = bk * 16 + ty;
    int nOut = bn * 16 + tx;
    int p = nOut >> 1;
    int orig = (nOut & 1) ? (HALF_ + p) : p;
    float v = (p < HALF_) ? W[((size_t)blk * HID_ + k) * D_ + orig] : 0.f;
    t[ty][tx] = v;
    __syncthreads();
    float o = t[tx][ty];
    __nv_bfloat16 h, l;
    split1(o, h, l);
    size_t oidx = ((size_t)blk * N2PAD + bn * 16 + ty) * K2PAD + bk * 16 + tx;
    hi[oidx] = h;
    lo[oidx] = l;
}

// ---------------- fused HMMA GEMM (3-stage pipeline, 1 sync/chunk, 2 CTAs/SM) ----------------
// MODE 0: hidden layer. C = relu(A@Bt^T + bias + Wcond[392+lab[m]]), write split bf16.
// MODE 1/2: output layer, interleaved (s,t) columns, fused coupling:
//   p = n/2; s = acc(n)+bias[p]; t = acc(n+1)+bias[392+p];
//   ls = 0.636*atan(s); y = exp(ls)*xo[m][p] + t; Yf[m*D_+p] = y; jac[m] += ls;
//   MODE 1 additionally writes split bf16 y (Chi/Clo stride K1PAD).
template<int MODE>
__global__ __launch_bounds__(256, 2)
void gemm_mma(const __nv_bfloat16* __restrict__ Ahi, const __nv_bfloat16* __restrict__ Alo,
              const __nv_bfloat16* __restrict__ Bhi, const __nv_bfloat16* __restrict__ Blo,
              int Ka, int nch,
              const float* __restrict__ bias,
              const float* __restrict__ Wcond, const int* __restrict__ lab,
              const float* __restrict__ xo,
              float* __restrict__ Yf, float* __restrict__ jac,
              __nv_bfloat16* __restrict__ Chi, __nv_bfloat16* __restrict__ Clo) {
    extern __shared__ __align__(128) char sm[];
    const int tid = threadIdx.x;
    const int lane = tid & 31, wid = tid >> 5;
    const int wm = wid & 3, wn = wid >> 2;           // 4x2 warp grid, 32x32 warp tiles
    const int m0 = blockIdx.y * TILE_M, n0 = blockIdx.x * TILE_N;
    const uint32_t sb = smem_u32(sm);

    const int a_row = tid >> 2, a_seg = tid & 3;
    const int b_row = tid >> 2, b_seg = tid & 3;

    float acc[2][4][4];
#pragma unroll
    for (int i = 0; i < 2; i++)
#pragma unroll
        for (int j = 0; j < 4; j++)
#pragma unroll
            for (int q = 0; q < 4; q++) acc[i][j][q] = 0.f;

#define LOAD_STAGE(c, s)                                                                  \
    do {                                                                                  \
        uint32_t st = sb + (s) * ST_SIZE;                                                 \
        const __nv_bfloat16* a0s = Ahi + (size_t)(m0 + a_row) * Ka + (c) * 32 + a_seg * 8;\
        const __nv_bfloat16* a1s = a0s + (size_t)64 * Ka;                                 \
        const __nv_bfloat16* a2s = Alo + (size_t)(m0 + a_row) * Ka + (c) * 32 + a_seg * 8;\
        const __nv_bfloat16* a3s = a2s + (size_t)64 * Ka;                                 \
        CP_ASYNC16(st + ST_AHI + a_row * SA_ROW + a_seg * 16, a0s);                       \
        CP_ASYNC16(st + ST_AHI + (a_row + 64) * SA_ROW + a_seg * 16, a1s);                \
        CP_ASYNC16(st + ST_ALO + a_row * SA_ROW + a_seg * 16, a2s);                       \
        CP_ASYNC16(st + ST_ALO + (a_row + 64) * SA_ROW + a_seg * 16, a3s);                \
        CP_ASYNC16(st + ST_BHI + b_row * SA_ROW + b_seg * 16,                             \
                   Bhi + (size_t)(n0 + b_row) * Ka + (c) * 32 + b_seg * 8);               \
        CP_ASYNC16(st + ST_BLO + b_row * SA_ROW + b_seg * 16,                             \
                   Blo + (size_t)(n0 + b_row) * Ka + (c) * 32 + b_seg * 8);               \
    } while (0)

    LOAD_STAGE(0, 0);
    CP_COMMIT();
    LOAD_STAGE(1, 1);
    CP_COMMIT();

    const uint32_t a_lrow = (lane & 15);
    const uint32_t a_lcol = (lane >> 4) << 4;
    const uint32_t b_lrow = (lane & 7) + ((lane & 16) >> 1);
    const uint32_t b_lcol = (lane & 8) << 1;

    int cs = 0, ls2 = 2;
    for (int c = 0; c < nch; c++) {
        CP_WAIT1();            // in-order retirement: stage c resident
        __syncthreads();       // all warps done with stage (c-1)%3; safe to overwrite
        if (c + 2 < nch) LOAD_STAGE(c + 2, ls2);
        CP_COMMIT();           // commit (possibly empty) keeps group count in sync

        uint32_t st = sb + cs * ST_SIZE;
#pragma unroll
        for (int s = 0; s < 2; s++) {
            uint32_t a[2][2][4];
            uint32_t b[2][4][2];
#pragma unroll
            for (int hl = 0; hl < 2; hl++) {
#pragma unroll
                for (int mm = 0; mm < 2; mm++) {
                    uint32_t ad = st + (hl ? ST_ALO : ST_AHI)
                                + (wm * 32 + mm * 16 + a_lrow) * SA_ROW + a_lcol + s * 32;
                    ldm4(a[hl][mm][0], a[hl][mm][1], a[hl][mm][2], a[hl][mm][3], ad);
                }
#pragma unroll
                for (int nt = 0; nt < 2; nt++) {
                    uint32_t bd = st + (hl ? ST_BLO : ST_BHI)
                                + (wn * 32 + nt * 16 + b_lrow) * SA_ROW + b_lcol + s * 32;
                    ldm4(b[hl][2 * nt][0], b[hl][2 * nt][1],
                         b[hl][2 * nt + 1][0], b[hl][2 * nt + 1][1], bd);
                }
            }
#pragma unroll
            for (int mm = 0; mm < 2; mm++) {
#pragma unroll
                for (int nn = 0; nn < 4; nn++) {
                    float* cc = acc[mm][nn];
                    mma_bf16(cc[0], cc[1], cc[2], cc[3],
                             a[0][mm][0], a[0][mm][1], a[0][mm][2], a[0][mm][3],
                             b[0][nn][0], b[0][nn][1]);
                    mma_bf16(cc[0], cc[1], cc[2], cc[3],
                             a[0][mm][0], a[0][mm][1], a[0][mm][2], a[0][mm][3],
                             b[1][nn][0], b[1][nn][1]);
                    mma_bf16(cc[0], cc[1], cc[2], cc[3],
                             a[1][mm][0], a[1][mm][1], a[1][mm][2], a[1][mm][3],
                             b[0][nn][0], b[0][nn][1]);
                }
            }
        }
        cs = (cs == STAGES - 1) ? 0 : cs + 1;
        ls2 = (ls2 == STAGES - 1) ? 0 : ls2 + 1;
    }
#undef LOAD_STAGE

    // ---- epilogue ----
    const int rbase = lane >> 2;
    const int cbase = (lane & 3) * 2;

    if (MODE == 0) {
#pragma unroll
        for (int mm = 0; mm < 2; mm++) {
#pragma unroll
            for (int h = 0; h < 2; h++) {
                int m = m0 + wm * 32 + mm * 16 + rbase + h * 8;
                const float* wc = Wcond + (size_t)(HALF_ + lab[m]) * HID_;
#pragma unroll
                for (int nn = 0; nn < 4; nn++) {
                    int n = n0 + wn * 32 + nn * 8 + cbase;
                    float v0 = acc[mm][nn][h * 2 + 0] + bias[n] + wc[n];
                    float v1 = acc[mm][nn][h * 2 + 1] + bias[n + 1] + wc[n + 1];
                    v0 = fmaxf(v0, 0.f);
                    v1 = fmaxf(v1, 0.f);
                    __nv_bfloat16 h0, l0, h1, l1;
                    split1(v0, h0, l0);
                    split1(v1, h1, l1);
                    __nv_bfloat162 hp; hp.x = h0; hp.y = h1;
                    __nv_bfloat162 lp; lp.x = l0; lp.y = l1;
                    *reinterpret_cast<__nv_bfloat162*>(Chi + (size_t)m * HID_ + n) = hp;
                    *reinterpret_cast<__nv_bfloat162*>(Clo + (size_t)m * HID_ + n) = lp;
                }
            }
        }
    } else {
#pragma unroll
        for (int mm = 0; mm < 2; mm++) {
#pragma unroll
            for (int h = 0; h < 2; h++) {
                int m = m0 + wm * 32 + mm * 16 + rbase + h * 8;
                float jl = 0.f;
#pragma unroll
                for (int nn = 0; nn < 4; nn++) {
                    int n = n0 + wn * 32 + nn * 8 + cbase;   // always even
                    int p = n >> 1;
                    if (p < HALF_) {
                        float s = acc[mm][nn][h * 2 + 0] + bias[p];
                        float t = acc[mm][nn][h * 2 + 1] + bias[HALF_ + p];
                        float ls = 0.636f * atanf(s);
                        float y = expf(ls) * xo[(size_t)m * HALF_ + p] + t;
                        Yf[(size_t)m * D_ + p] = y;
                        if (MODE == 1) {
                            __nv_bfloat16 yhh, yll;
                            split1(y, yhh, yll);
                            Chi[(size_t)m * K1PAD + p] = yhh;
                            Clo[(size_t)m * K1PAD + p] = yll;
                        }
                        jl += ls;
                    }
                }
                jl += __shfl_xor_sync(0xffffffffu, jl, 1);
                jl += __shfl_xor_sync(0xffffffffu, jl, 2);
                if ((lane & 3) == 0) atomicAdd(&jac[m], jl);
            }
        }
    }
}

// ---------------- host launcher ----------------
extern "C" void kernel_launch(void* const* d_in, const int* in_sizes, int n_in,
                              void* d_out, int out_size) {
    const float* x     = (const float*)d_in[0];
    const int*   l     = (const int*)  d_in[1];
    const int*   perms = (const int*)  d_in[2];
    const float* s1_W1 = (const float*)d_in[3];
    const float* s1_b1 = (const float*)d_in[4];
    const float* s1_W2 = (const float*)d_in[5];
    const float* s1_b2 = (const float*)d_in[6];
    const float* s2_W1 = (const float*)d_in[7];
    const float* s2_b1 = (const float*)d_in[8];
    const float* s2_W2 = (const float*)d_in[9];
    const float* s2_b2 = (const float*)d_in[10];

    float* z   = (float*)d_out;
    float* jac = z + (size_t)B_ * D_;

    float *pv, *pxa, *pxb;
    cudaGetSymbolAddress((void**)&pv,  g_v);
    cudaGetSymbolAddress((void**)&pxa, g_xa);
    cudaGetSymbolAddress((void**)&pxb, g_xb);

    __nv_bfloat16 *xbh, *xbl, *ysh, *ysl, *hh, *hl;
    cudaGetSymbolAddress((void**)&xbh, g_xbh);
    cudaGetSymbolAddress((void**)&xbl, g_xbl);
    cudaGetSymbolAddress((void**)&ysh, g_ysh);
    cudaGetSymbolAddress((void**)&ysl, g_ysl);
    cudaGetSymbolAddress((void**)&hh,  g_hh);
    cudaGetSymbolAddress((void**)&hl,  g_hl);

    __nv_bfloat16 *w1h[2], *w1l[2], *w2h[2], *w2l[2];
    cudaGetSymbolAddress((void**)&w1h[0], g_s1w1_hi);
    cudaGetSymbolAddress((void**)&w1l[0], g_s1w1_lo);
    cudaGetSymbolAddress((void**)&w1h[1], g_s2w1_hi);
    cudaGetSymbolAddress((void**)&w1l[1], g_s2w1_lo);
    cudaGetSymbolAddress((void**)&w2h[0], g_s1w2_hi);
    cudaGetSymbolAddress((void**)&w2l[0], g_s1w2_lo);
    cudaGetSymbolAddress((void**)&w2h[1], g_s2w2_hi);
    cudaGetSymbolAddress((void**)&w2l[1], g_s2w2_lo);

    cudaFuncSetAttribute(gemm_mma<0>, cudaFuncAttributeMaxDynamicSharedMemorySize, SM_TOTAL);
    cudaFuncSetAttribute(gemm_mma<1>, cudaFuncAttributeMaxDynamicSharedMemorySize, SM_TOTAL);
    cudaFuncSetAttribute(gemm_mma<2>, cudaFuncAttributeMaxDynamicSharedMemorySize, SM_TOTAL);

    // persistent side streams/events (created once; deterministic work per call)
    static cudaStream_t st[2];
    static cudaEvent_t evFork, evJ[2];
    static bool inited = false;
    if (!inited) {
        for (int i = 0; i < 2; i++) {
            cudaStreamCreateWithFlags(&st[i], cudaStreamNonBlocking);
            cudaEventCreateWithFlags(&evJ[i], cudaEventDisableTiming);
        }
        cudaEventCreateWithFlags(&evFork, cudaEventDisableTiming);
        inited = true;
    }

    // ---- shared prologue on origin stream ----
    convert_w1_kernel<<<dim3(K1PAD / 16, HID_ / 16, 2 * NBLK_), 256>>>(
        s1_W1, s2_W1, w1h[0], w1l[0], w1h[1], w1l[1]);
    convert_w2_kernel<<<dim3(K2PAD / 16, N2PAD / 16, 2 * NBLK_), 256>>>(
        s1_W2, s2_W2, w2h[0], w2l[0], w2h[1], w2l[1]);
    init_kernel<<<(B_ * (K1PAD - HALF_) + 255) / 256, 256>>>(jac, xbh, xbl, ysh, ysl);

    // ---- fork: side streams wait on prologue; origin stream runs chain 0 ----
    cudaEventRecord(evFork, 0);
    cudaStreamWaitEvent(st[0], evFork, 0);
    cudaStreamWaitEvent(st[1], evFork, 0);

    // chain row split (multiples of TILE_M): 1408 / 1408 / 1280
    const int rowsArr[3] = {1408, 1408, 1280};
    const int offArr[3]  = {0, 1408, 2816};
    cudaStream_t strArr[3] = {(cudaStream_t)0, st[0], st[1]};

    const size_t W1sz  = (size_t)(HALF_ + CONDN_) * HID_;
    const size_t W1tsz = (size_t)HID_ * K1PAD;
    const size_t W2tsz = (size_t)N2PAD * K2PAD;

    for (int c = 0; c < 3; c++) {
        cudaStream_t s = strArr[c];
        const int rows = rowsArr[c];
        const size_t off = (size_t)offArr[c];

        const dim3 g1Grid(HID_ / TILE_N,  rows / TILE_M);
        const dim3 g2Grid(N2PAD / TILE_N, rows / TILE_M);
        const int permGrid = (rows * DQ_ + 255) / 256;

        const float* xH  = x   + off * D_;
        float* pvH       = pv  + off * D_;
        float* zH        = z   + off * D_;
        float* jacH      = jac + off;
        const int* lH    = l   + off;
        float* xaH = pxa + off * HALF_;
        float* xbH = pxb + off * HALF_;
        __nv_bfloat16* xbhH = xbh + off * K1PAD;
        __nv_bfloat16* xblH = xbl + off * K1PAD;
        __nv_bfloat16* yshH = ysh + off * K1PAD;
        __nv_bfloat16* yslH = ysl + off * K1PAD;
        __nv_bfloat16* hhH  = hh  + off * K2PAD;
        __nv_bfloat16* hlH  = hl  + off * K2PAD;

        for (int k = 0; k < NBLK_; k++) {
            const float* vsrc = (k == 0) ? xH : pvH;
            float* vdst = (k == NBLK_ - 1) ? zH : pvH;

            permute_kernel<<<permGrid, 256, 0, s>>>(
                vsrc, perms + (size_t)k * D_, xaH, xbH, xbhH, xblH, rows);

            // subnet s2: hidden, then output+coupling -> y1 (fp32 vdst + split)
            gemm_mma<0><<<g1Grid, 256, SM_TOTAL, s>>>(
                xbhH, xblH, w1h[1] + k * W1tsz, w1l[1] + k * W1tsz, K1PAD, K1PAD / TILE_K,
                s2_b1 + (size_t)k * HID_, s2_W1 + k * W1sz, lH,
                nullptr, nullptr, nullptr, hhH, hlH);
            gemm_mma<1><<<g2Grid, 256, SM_TOTAL, s>>>(
                hhH, hlH, w2h[1] + k * W2tsz, w2l[1] + k * W2tsz, K2PAD, K2PAD / TILE_K,
                s2_b2 + (size_t)k * D_, nullptr, nullptr,
                xaH, vdst, jacH, yshH, yslH);

            // subnet s1: hidden, then output+coupling -> y2 (fp32 vdst+HALF_)
            gemm_mma<0><<<g1Grid, 256, SM_TOTAL, s>>>(
                yshH, yslH, w1h[0] + k * W1tsz, w1l[0] + k * W1tsz, K1PAD, K1PAD / TILE_K,
                s1_b1 + (size_t)k * HID_, s1_W1 + k * W1sz, lH,
                nullptr, nullptr, nullptr, hhH, hlH);
            gemm_mma<2><<<g2Grid, 256, SM_TOTAL, s>>>(
                hhH, hlH, w2h[0] + k * W2tsz, w2l[0] + k * W2tsz, K2PAD, K2PAD / TILE_K,
                s1_b2 + (size_t)k * D_, nullptr, nullptr,
                xbH, vdst + HALF_, jacH, nullptr, nullptr);
        }
    }

    // ---- join side streams into origin ----
    cudaEventRecord(evJ[0], st[0]);
    cudaEventRecord(evJ[1], st[1]);
    cudaStreamWaitEvent(0, evJ[0], 0);
    cudaStreamWaitEvent(0, evJ[1], 0);
}